// round 16
// baseline (speedup 1.0000x reference)
#include <cuda_runtime.h>
#include <cuda_bf16.h>
#include <cuda_fp16.h>
#include <cstdint>

// Problem constants (fixed by the dataset)
constexpr int U_N  = 50000;
constexpr int I_N  = 100000;
constexpr int N_N  = 150000;   // U + I
constexpr int D    = 64;
constexpr int B_N  = 8192;
constexpr int HID  = 128;

constexpr int NTOT  = N_N + 2 * U_N + 2 * I_N;   // 450000 CSR rows (5 graphs)
constexpr int NSCAN = NTOT + 1;
constexpr int E_TOT = 5000000;

// int scratch layout
constexpr int OFF_DEG  = 0;
constexpr int DEG_PAD  = 450008;
constexpr int OFF_CNT  = DEG_PAD;                // cursor array (init = S by scan23w)
constexpr int CNT_PAD  = 450008;
constexpr int OFF_DOUT = OFF_CNT + CNT_PAD;
constexpr int DOUT_LEN = 2 * U_N + 2 * I_N;      // 300000
constexpr int OFF_PART = OFF_DOUT + DOUT_LEN;
constexpr int INT_TOT  = OFF_PART + 256;

// CSR row bases within the concatenated degree/scan vector
constexpr int RB_GCN = 0;
constexpr int RB_U1  = N_N;
constexpr int RB_U2  = N_N + U_N;
constexpr int RB_I1  = N_N + 2 * U_N;
constexpr int RB_I2  = N_N + 2 * U_N + I_N;

// attention tiling (16-row tiles, 8 warps/block, one tile per warp)
constexpr int NTU   = (2 * U_N) / 16;            // 6250
constexpr int NTI   = (2 * I_N) / 16;            // 12500
constexpr int BLK_U = (NTU + 7) / 8;             // 782
constexpr int BLK_I = (NTI + 7) / 8;             // 1563
constexpr int GRID_ATTN = BLK_U + BLK_I;         // 2345
constexpr int GRID_GCN  = (N_N * 8 + 255) / 256; // 4688 (8 lanes/row, ceil)
constexpr int GRID_FUSE = GRID_ATTN + GRID_GCN;

constexpr int GRID_INIT = (N_N * 16) / 256;      // 9375 (init part of initcnt)

// ---------------------------------------------------------------------------
// Scratch (device globals: allocation-free)
// ---------------------------------------------------------------------------
__device__ __align__(256) __half g_ui16_a[N_N * D];   // fp16 gather ping
__device__ __align__(256) __half g_ui16_b[N_N * D];   // fp16 gather pong
__device__ __align__(256) float  g_ui32[N_N * D];     // fp32 final gcn output
__device__ __align__(256) __half g_hu16[U_N * D];
__device__ __align__(256) __half g_hi16[I_N * D];
__device__ __align__(256) float  g_zu[U_N * 2 * D];
__device__ __align__(256) float  g_zi[I_N * 2 * D];
__device__ __align__(256) float  g_wdst[NTOT];
__device__ __align__(256) float  g_wsrc[DOUT_LEN];
__device__ __align__(256) float  g_wsum[4];
__device__ __align__(256) int    g_int[INT_TOT];
__device__ __align__(256) int    g_S[NSCAN + 8];
__device__ __align__(256) int    g_csr[E_TOT];

// ---------------------------------------------------------------------------
// Helpers
// ---------------------------------------------------------------------------
__device__ __forceinline__ float tanh_fast(float x) {
    float y;
    asm("tanh.approx.f32 %0, %1;" : "=f"(y) : "f"(x));
    return y;
}
__device__ __forceinline__ uint32_t pack_bf16(float lo, float hi) {
    uint32_t r;
    asm("cvt.rn.bf16x2.f32 %0, %1, %2;" : "=r"(r) : "f"(hi), "f"(lo));
    return r;
}
__device__ __forceinline__ void mma16816(float c[4], const uint32_t a[4],
                                         uint32_t b0, uint32_t b1) {
    asm volatile(
        "mma.sync.aligned.m16n8k16.row.col.f32.bf16.bf16.f32 "
        "{%0,%1,%2,%3}, {%4,%5,%6,%7}, {%8,%9}, {%0,%1,%2,%3};"
        : "+f"(c[0]), "+f"(c[1]), "+f"(c[2]), "+f"(c[3])
        : "r"(a[0]), "r"(a[1]), "r"(a[2]), "r"(a[3]), "r"(b0), "r"(b1));
}
__device__ __forceinline__ float2 beta_pair(const float* __restrict__ wsum,
                                            int off, float inv_n) {
    float a = wsum[off] * inv_n;
    float b = wsum[off + 1] * inv_n;
    float m = fmaxf(a, b);
    float e0 = expf(a - m), e1 = expf(b - m);
    float inv = 1.f / (e0 + e1);
    return make_float2(e0 * inv, e1 * inv);
}

// 8 fp32 accumulator
struct f8 { float4 a, b; };
// accumulate w * (8 halves loaded as uint4) into f8
__device__ __forceinline__ void acc_h8(f8& acc, float w, const uint4* row, int lane) {
    uint4 v = row[lane];
    float2 f0 = __half22float2(*(const __half2*)&v.x);
    float2 f1 = __half22float2(*(const __half2*)&v.y);
    float2 f2 = __half22float2(*(const __half2*)&v.z);
    float2 f3 = __half22float2(*(const __half2*)&v.w);
    acc.a.x = fmaf(w, f0.x, acc.a.x); acc.a.y = fmaf(w, f0.y, acc.a.y);
    acc.a.z = fmaf(w, f1.x, acc.a.z); acc.a.w = fmaf(w, f1.y, acc.a.w);
    acc.b.x = fmaf(w, f2.x, acc.b.x); acc.b.y = fmaf(w, f2.y, acc.b.y);
    acc.b.z = fmaf(w, f3.x, acc.b.z); acc.b.w = fmaf(w, f3.y, acc.b.w);
}

// ---------------------------------------------------------------------------
// Kernels
// ---------------------------------------------------------------------------
__global__ void zero_i4_k(int4* p, int n4) {
    int t = blockIdx.x * blockDim.x + threadIdx.x;
    if (t < n4) p[t] = make_int4(0, 0, 0, 0);
}

// ---------------------------------------------------------------------------
// FUSED init + degree counting (cnt: 4 edges/thread — saturation point)
// ---------------------------------------------------------------------------
struct CntJobs {
    const int* ptr[9];
    int        dego[9];
    int        E[9];
    int        qcum[10];
};

__global__ void initcnt_k(const float4* __restrict__ uf, const float4* __restrict__ itf,
                          CntJobs J) {
    if (blockIdx.x < GRID_INIT) {
        int t = blockIdx.x * blockDim.x + threadIdx.x;   // handles 4 floats
        float4 v;
        __half2* hdst;
        int hidx;
        if (t < U_N * 16) {
            v = uf[t];
            hdst = (__half2*)g_hu16; hidx = 2 * t;
        } else {
            v = itf[t - U_N * 16];
            hdst = (__half2*)g_hi16; hidx = 2 * (t - U_N * 16);
        }
        __half2 h0 = __floats2half2_rn(v.x, v.y);
        __half2 h1 = __floats2half2_rn(v.z, v.w);
        ((__half2*)g_ui16_a)[2 * t]     = h0;
        ((__half2*)g_ui16_a)[2 * t + 1] = h1;
        hdst[hidx]     = h0;
        hdst[hidx + 1] = h1;
        return;
    }
    int t = (blockIdx.x - GRID_INIT) * blockDim.x + threadIdx.x;
    if (t >= J.qcum[9]) return;
    int j = 0;
    #pragma unroll
    for (int k = 1; k < 9; k++) j += (t >= J.qcum[k]);
    int e0 = (t - J.qcum[j]) * 4;
    int E = J.E[j];
    const int* p = J.ptr[j];
    int* base = g_int + J.dego[j];
    #pragma unroll
    for (int i = 0; i < 4; i++) {
        int e = e0 + i;
        if (e < E) atomicAdd(&base[p[e]], 1);
    }
}

// --- scan phase 1 ---
__global__ void scan1_k(const int* __restrict__ deg, int n,
                        int* __restrict__ S, int* __restrict__ part) {
    __shared__ int warpsum[8];
    int base = blockIdx.x * 2048 + threadIdx.x * 8;
    int v[8];
    int s = 0;
    #pragma unroll
    for (int i = 0; i < 8; i++) {
        int x = (base + i < n) ? deg[base + i] : 0;
        v[i] = s; s += x;
    }
    int lane = threadIdx.x & 31, w = threadIdx.x >> 5;
    int ts = s;
    #pragma unroll
    for (int o = 1; o < 32; o <<= 1) {
        int y = __shfl_up_sync(0xffffffffu, ts, o);
        if (lane >= o) ts += y;
    }
    if (lane == 31) warpsum[w] = ts;
    __syncthreads();
    if (w == 0 && lane < 8) {
        int x = warpsum[lane];
        #pragma unroll
        for (int o = 1; o < 8; o <<= 1) {
            int y = __shfl_up_sync(0xffu, x, o);
            if (lane >= o) x += y;
        }
        warpsum[lane] = x;
    }
    __syncthreads();
    int prefix = (w > 0 ? warpsum[w - 1] : 0) + (ts - s);
    #pragma unroll
    for (int i = 0; i < 8; i++)
        if (base + i < n) S[base + i] = prefix + v[i];
    if (threadIdx.x == 0) part[blockIdx.x] = warpsum[7];
}

// --- scan phase 2+3 fused with cursor init + weights ---
__global__ void scan23w_k(int nchunks) {
    __shared__ int sh[256];
    {
        int t = threadIdx.x;
        int x = (t < nchunks) ? g_int[OFF_PART + t] : 0;
        sh[t] = x;
        __syncthreads();
        for (int o = 1; o < 256; o <<= 1) {
            int y = (t >= o) ? sh[t - o] : 0;
            __syncthreads();
            sh[t] += y;
            __syncthreads();
        }
    }
    int psum = (blockIdx.x > 0) ? sh[blockIdx.x - 1] : 0;
    int base = blockIdx.x * 2048 + threadIdx.x * 8;
    #pragma unroll
    for (int i = 0; i < 8; i++) {
        int t = base + i;
        if (t >= NSCAN) break;
        int sv = g_S[t] + psum;
        g_S[t] = sv;
        if (t < NTOT) {
            g_int[OFF_CNT + t] = sv;
            float d = (float)g_int[OFF_DEG + t];
            g_wdst[t] = (t < N_N) ? ((d > 0.f) ? rsqrtf(d) : 0.f)
                                  : rsqrtf(fmaxf(d, 1.f));
        }
        if (t < DOUT_LEN)
            g_wsrc[t] = rsqrtf(fmaxf((float)g_int[OFF_DOUT + t], 1.f));
    }
}

// ---------------------------------------------------------------------------
// Fused CSR fill (4 edges/thread, direct global cursor)
// ---------------------------------------------------------------------------
struct FillJobs {
    const int* src[5];
    const int* dst[5];
    int        rb[5];
    int        E[5];
    int        qcum[6];
};

__global__ void fill_all_k(FillJobs J) {
    int t = blockIdx.x * blockDim.x + threadIdx.x;
    if (t >= J.qcum[5]) return;
    int j = 0;
    #pragma unroll
    for (int k = 1; k < 5; k++) j += (t >= J.qcum[k]);
    int e0 = (t - J.qcum[j]) * 4;
    int E = J.E[j];
    const int* src = J.src[j];
    const int* dst = J.dst[j];
    int* cur = g_int + OFF_CNT + J.rb[j];
    #pragma unroll
    for (int i = 0; i < 4; i++) {
        int e = e0 + i;
        if (e < E) {
            int p = atomicAdd(&cur[dst[e]], 1);
            g_csr[p] = src[e];
        }
    }
}

// ---------------------------------------------------------------------------
// fp16 CSR pull body: QUARTER-warp (8 lanes) per row, uint4 (16B) payload,
// 8-edge deep main loop -> up to 32 independent gathers in flight per warp.
// ---------------------------------------------------------------------------
__device__ __forceinline__ f8 pull_row16(const int* __restrict__ S,
                                         const int* __restrict__ csr,
                                         const float* __restrict__ wsrc,
                                         const float* __restrict__ wdst,
                                         const uint4* __restrict__ in,  // row stride 8 uint4
                                         int r, int lane) {
    int s = S[r], e = S[r + 1];
    f8 acc;
    acc.a = make_float4(0.f, 0.f, 0.f, 0.f);
    acc.b = make_float4(0.f, 0.f, 0.f, 0.f);
    int j = s;
    for (; j + 8 <= e; j += 8) {
        int c0 = csr[j],     c1 = csr[j + 1], c2 = csr[j + 2], c3 = csr[j + 3];
        int c4 = csr[j + 4], c5 = csr[j + 5], c6 = csr[j + 6], c7 = csr[j + 7];
        float w0 = wsrc[c0], w1 = wsrc[c1], w2 = wsrc[c2], w3 = wsrc[c3];
        float w4 = wsrc[c4], w5 = wsrc[c5], w6 = wsrc[c6], w7 = wsrc[c7];
        acc_h8(acc, w0, in + (size_t)c0 * 8, lane);
        acc_h8(acc, w1, in + (size_t)c1 * 8, lane);
        acc_h8(acc, w2, in + (size_t)c2 * 8, lane);
        acc_h8(acc, w3, in + (size_t)c3 * 8, lane);
        acc_h8(acc, w4, in + (size_t)c4 * 8, lane);
        acc_h8(acc, w5, in + (size_t)c5 * 8, lane);
        acc_h8(acc, w6, in + (size_t)c6 * 8, lane);
        acc_h8(acc, w7, in + (size_t)c7 * 8, lane);
    }
    for (; j + 4 <= e; j += 4) {
        int c0 = csr[j], c1 = csr[j + 1], c2 = csr[j + 2], c3 = csr[j + 3];
        float w0 = wsrc[c0], w1 = wsrc[c1], w2 = wsrc[c2], w3 = wsrc[c3];
        acc_h8(acc, w0, in + (size_t)c0 * 8, lane);
        acc_h8(acc, w1, in + (size_t)c1 * 8, lane);
        acc_h8(acc, w2, in + (size_t)c2 * 8, lane);
        acc_h8(acc, w3, in + (size_t)c3 * 8, lane);
    }
    for (; j < e; j++) {
        int c = csr[j];
        acc_h8(acc, wsrc[c], in + (size_t)c * 8, lane);
    }
    float wd = wdst[r];
    acc.a.x *= wd; acc.a.y *= wd; acc.a.z *= wd; acc.a.w *= wd;
    acc.b.x *= wd; acc.b.y *= wd; acc.b.z *= wd; acc.b.w *= wd;
    return acc;
}

// ---------------------------------------------------------------------------
// Fused HAN pulls: all 4 metapath graphs (300K rows, 8 lanes/row), fp16 in,
// fp32 z out; also resets wsum for the following attention kernel.
// ---------------------------------------------------------------------------
__global__ void hanpull_k() {
    if (blockIdx.x == 0 && threadIdx.x < 4) g_wsum[threadIdx.x] = 0.f;
    int gid = blockIdx.x * blockDim.x + threadIdx.x;
    int gr = gid >> 3;   // 0 .. 300K
    if (gr >= 2 * U_N + 2 * I_N) return;
    int lane = gid & 7;
    int R = RB_U1 + gr;

    const uint4* in;
    float* out;
    const float* ws;
    int ooff, lr;
    if (gr < U_N)                { in = (const uint4*)g_hu16; out = g_zu; ws = g_wsrc;                 ooff = 0;  lr = gr; }
    else if (gr < 2 * U_N)       { in = (const uint4*)g_hu16; out = g_zu; ws = g_wsrc + U_N;           ooff = 64; lr = gr - U_N; }
    else if (gr < 2 * U_N + I_N) { in = (const uint4*)g_hi16; out = g_zi; ws = g_wsrc + 2 * U_N;       ooff = 0;  lr = gr - 2 * U_N; }
    else                         { in = (const uint4*)g_hi16; out = g_zi; ws = g_wsrc + 2 * U_N + I_N; ooff = 64; lr = gr - 2 * U_N - I_N; }

    f8 o = pull_row16(g_S, g_csr, ws, g_wdst, in, R, lane);
    float* dst = out + (size_t)lr * 128 + ooff + lane * 8;
    *(float4*)dst       = o.a;
    *(float4*)(dst + 4) = o.b;
}

// ---------------------------------------------------------------------------
// FUSED: HAN attention (user+item, tensor cores) co-resident with gcn pull.
// gcn pull: fp16 in, 8 lanes/row; iter0 writes fp16 pong, iter1 fp32 g_ui32.
// ---------------------------------------------------------------------------
constexpr int WT_STRIDE = 72;

__global__ void gcn_attn_k(const uint4* __restrict__ ui_in16,
                           uint4* __restrict__ ui_out16,
                           float* __restrict__ ui_out32, int last,
                           const float* __restrict__ W1u, const float* __restrict__ b1u,
                           const float* __restrict__ w2u,
                           const float* __restrict__ W1i, const float* __restrict__ b1i,
                           const float* __restrict__ w2i) {
    if (blockIdx.x >= GRID_ATTN) {
        // ---- gcn pull path ----
        int gid = (blockIdx.x - GRID_ATTN) * blockDim.x + threadIdx.x;
        int r = gid >> 3;
        if (r < N_N) {
            int lane = gid & 7;
            f8 o = pull_row16(g_S + RB_GCN, g_csr, g_wdst + RB_GCN,
                              g_wdst + RB_GCN, ui_in16, r, lane);
            if (last) {
                float* dst = ui_out32 + (size_t)r * D + lane * 8;
                *(float4*)dst       = o.a;
                *(float4*)(dst + 4) = o.b;
            } else {
                uint4 hv;
                *(__half2*)&hv.x = __floats2half2_rn(o.a.x, o.a.y);
                *(__half2*)&hv.y = __floats2half2_rn(o.a.z, o.a.w);
                *(__half2*)&hv.z = __floats2half2_rn(o.b.x, o.b.y);
                *(__half2*)&hv.w = __floats2half2_rn(o.b.z, o.b.w);
                ui_out16[(size_t)r * 8 + lane] = hv;
            }
        }
        return;
    }

    // ---- attention path (fp32 zu/zi, unchanged) ----
    bool isU = blockIdx.x < BLK_U;
    const float* z  = isU ? g_zu : g_zi;
    const float* W1 = isU ? W1u : W1i;
    const float* b1 = isU ? b1u : b1i;
    const float* w2 = isU ? w2u : w2i;
    int ntiles = isU ? NTU : NTI;
    int bid    = isU ? blockIdx.x : blockIdx.x - BLK_U;
    float* wsp = g_wsum + (isU ? 0 : 2);

    __shared__ __align__(16) __nv_bfloat16 Wt[HID * WT_STRIDE];
    __shared__ float b1s[HID];
    __shared__ float w2s[HID];
    __shared__ float r0s[256], r1s[256];

    for (int i = threadIdx.x; i < D * HID; i += blockDim.x) {
        int k = i >> 7, h = i & 127;
        Wt[h * WT_STRIDE + k] = __float2bfloat16(W1[i]);
    }
    if (threadIdx.x < HID) {
        b1s[threadIdx.x] = b1[threadIdx.x];
        w2s[threadIdx.x] = w2[threadIdx.x];
    }
    __syncthreads();

    int warp = threadIdx.x >> 5;
    int lane = threadIdx.x & 31;
    int g = lane >> 2;
    int tig = lane & 3;
    int tile = bid * 8 + warp;

    float acc0 = 0.f, acc1 = 0.f;

    if (tile < ntiles) {
        const float* zb = z + (size_t)tile * 16 * D;
        uint32_t A[4][4];
        #pragma unroll
        for (int kt = 0; kt < 4; kt++) {
            int k0 = kt * 16 + tig * 2;
            float2 v;
            v = *(const float2*)(zb + g * D + k0);            A[kt][0] = pack_bf16(v.x, v.y);
            v = *(const float2*)(zb + (g + 8) * D + k0);      A[kt][1] = pack_bf16(v.x, v.y);
            v = *(const float2*)(zb + g * D + k0 + 8);        A[kt][2] = pack_bf16(v.x, v.y);
            v = *(const float2*)(zb + (g + 8) * D + k0 + 8);  A[kt][3] = pack_bf16(v.x, v.y);
        }
        float s0 = 0.f, s1 = 0.f;
        #pragma unroll
        for (int nt = 0; nt < 16; nt++) {
            float c[4] = {0.f, 0.f, 0.f, 0.f};
            const __nv_bfloat16* wrow = Wt + (nt * 8 + g) * WT_STRIDE;
            #pragma unroll
            for (int kt = 0; kt < 4; kt++) {
                uint32_t b0 = *(const uint32_t*)(wrow + kt * 16 + tig * 2);
                uint32_t b1v = *(const uint32_t*)(wrow + kt * 16 + tig * 2 + 8);
                mma16816(c, A[kt], b0, b1v);
            }
            int col0 = nt * 8 + tig * 2;
            float bb0 = b1s[col0], bb1 = b1s[col0 + 1];
            float ww0 = w2s[col0], ww1 = w2s[col0 + 1];
            s0 = fmaf(tanh_fast(c[0] + bb0), ww0, s0);
            s0 = fmaf(tanh_fast(c[1] + bb1), ww1, s0);
            s1 = fmaf(tanh_fast(c[2] + bb0), ww0, s1);
            s1 = fmaf(tanh_fast(c[3] + bb1), ww1, s1);
        }
        s0 += __shfl_xor_sync(0xffffffffu, s0, 1);
        s0 += __shfl_xor_sync(0xffffffffu, s0, 2);
        s1 += __shfl_xor_sync(0xffffffffu, s1, 1);
        s1 += __shfl_xor_sync(0xffffffffu, s1, 2);
        if (tig == 0) {
            float v = s0 + s1;
            if (g & 1) acc1 += v; else acc0 += v;
        }
    }

    r0s[threadIdx.x] = acc0;
    r1s[threadIdx.x] = acc1;
    __syncthreads();
    for (int s = blockDim.x >> 1; s > 0; s >>= 1) {
        if (threadIdx.x < s) {
            r0s[threadIdx.x] += r0s[threadIdx.x + s];
            r1s[threadIdx.x] += r1s[threadIdx.x + s];
        }
        __syncthreads();
    }
    if (threadIdx.x == 0) {
        atomicAdd(&wsp[0], r0s[0]);
        atomicAdd(&wsp[1], r1s[0]);
    }
}

// ---------------------------------------------------------------------------
// Fused combine (user + item), beta inline; writes fp16 h (iteration 1 only)
// ---------------------------------------------------------------------------
__global__ void combine_all_k() {
    int t = blockIdx.x * blockDim.x + threadIdx.x;
    if (t >= (U_N + I_N) * 16) return;
    int node = t >> 4;
    int c = t & 15;
    const float4* z;
    __half2* h;
    float2 bb;
    if (node < U_N) {
        z = (const float4*)g_zu; h = (__half2*)g_hu16;
        bb = beta_pair(g_wsum, 0, 1.0f / U_N);
    } else {
        node -= U_N;
        z = (const float4*)g_zi; h = (__half2*)g_hi16;
        bb = beta_pair(g_wsum, 2, 1.0f / I_N);
    }
    float4 z0 = z[node * 32 + c];
    float4 z1 = z[node * 32 + 16 + c];
    float rx = fmaf(bb.x, z0.x, bb.y * z1.x);
    float ry = fmaf(bb.x, z0.y, bb.y * z1.y);
    float rz = fmaf(bb.x, z0.z, bb.y * z1.z);
    float rw = fmaf(bb.x, z0.w, bb.y * z1.w);
    h[node * 32 + c * 2]     = __floats2half2_rn(rx, ry);
    h[node * 32 + c * 2 + 1] = __floats2half2_rn(rz, rw);
}

// epilogue: iter-2 combine fused into the batched gathers; beta inline
__global__ void out_k(const int* __restrict__ uidx, const int* __restrict__ iidx,
                      const int* __restrict__ nidx, float* __restrict__ out) {
    int t = blockIdx.x * blockDim.x + threadIdx.x;
    if (t >= B_N * 16) return;
    int b = t >> 4;
    int c = t & 15;
    const float4* zu4 = (const float4*)g_zu;
    const float4* zi4 = (const float4*)g_zi;
    const float4* ui4 = (const float4*)g_ui32;
    float4* o4 = (float4*)out;
    float2 bU = beta_pair(g_wsum, 0, 1.0f / U_N);
    float2 bI = beta_pair(g_wsum, 2, 1.0f / I_N);

    {
        int u = uidx[b];
        float4 z0 = zu4[u * 32 + c];
        float4 z1 = zu4[u * 32 + 16 + c];
        float4 g = ui4[u * 16 + c];
        float4 r;
        r.x = 0.5f * (fmaf(bU.x, z0.x, bU.y * z1.x) + g.x);
        r.y = 0.5f * (fmaf(bU.x, z0.y, bU.y * z1.y) + g.y);
        r.z = 0.5f * (fmaf(bU.x, z0.z, bU.y * z1.z) + g.z);
        r.w = 0.5f * (fmaf(bU.x, z0.w, bU.y * z1.w) + g.w);
        o4[t] = r;
    }
    {
        int it = iidx[b];
        float4 z0 = zi4[it * 32 + c];
        float4 z1 = zi4[it * 32 + 16 + c];
        float4 g = ui4[(U_N + it) * 16 + c];
        float4 r;
        r.x = 0.5f * (fmaf(bI.x, z0.x, bI.y * z1.x) + g.x);
        r.y = 0.5f * (fmaf(bI.x, z0.y, bI.y * z1.y) + g.y);
        r.z = 0.5f * (fmaf(bI.x, z0.z, bI.y * z1.z) + g.z);
        r.w = 0.5f * (fmaf(bI.x, z0.w, bI.y * z1.w) + g.w);
        o4[B_N * 16 + t] = r;
    }
    {
        int itn = iidx[nidx[b]];
        float4 z0 = zi4[itn * 32 + c];
        float4 z1 = zi4[itn * 32 + 16 + c];
        float4 g = ui4[(U_N + itn) * 16 + c];
        float4 r;
        r.x = 0.5f * (fmaf(bI.x, z0.x, bI.y * z1.x) + g.x);
        r.y = 0.5f * (fmaf(bI.x, z0.y, bI.y * z1.y) + g.y);
        r.z = 0.5f * (fmaf(bI.x, z0.z, bI.y * z1.z) + g.z);
        r.w = 0.5f * (fmaf(bI.x, z0.w, bI.y * z1.w) + g.w);
        o4[2 * B_N * 16 + t] = r;
    }
}

// ---------------------------------------------------------------------------
// Host
// ---------------------------------------------------------------------------
static inline int nblk(long long n) { return (int)((n + 255) / 256); }

extern "C" void kernel_launch(void* const* d_in, const int* in_sizes, int n_in,
                              void* d_out, int out_size) {
    const float* user_feat = (const float*)d_in[0];
    const float* item_feat = (const float*)d_in[1];
    const float* sa_u_W1   = (const float*)d_in[2];
    const float* sa_u_b1   = (const float*)d_in[3];
    const float* sa_u_w2   = (const float*)d_in[4];
    const float* sa_i_W1   = (const float*)d_in[5];
    const float* sa_i_b1   = (const float*)d_in[6];
    const float* sa_i_w2   = (const float*)d_in[7];
    const int*   ui_e      = (const int*)d_in[8];
    const int*   ue1       = (const int*)d_in[9];
    const int*   ue2       = (const int*)d_in[10];
    const int*   ie1       = (const int*)d_in[11];
    const int*   ie2       = (const int*)d_in[12];
    const int*   uidx      = (const int*)d_in[13];
    const int*   iidx      = (const int*)d_in[14];
    const int*   nidx      = (const int*)d_in[15];

    const int Eui = in_sizes[8]  / 2;   // 2,000,000
    const int Eu  = in_sizes[9]  / 2;   //   500,000
    const int Ei  = in_sizes[11] / 2;   // 1,000,000

    __half *ui16_a, *ui16_b;
    float* ui32;
    int *ibuf, *S;
    cudaGetSymbolAddress((void**)&ui16_a, g_ui16_a);
    cudaGetSymbolAddress((void**)&ui16_b, g_ui16_b);
    cudaGetSymbolAddress((void**)&ui32,   g_ui32);
    cudaGetSymbolAddress((void**)&ibuf,   g_int);
    cudaGetSymbolAddress((void**)&S,      g_S);

    const int T = 256;

    // ---- zero int scratch ----
    zero_i4_k<<<nblk(INT_TOT / 4), T>>>((int4*)ibuf, INT_TOT / 4);

    // ---- fused init + degree counting (4 edges/thread) ----
    CntJobs cj;
    const int* cp[9]  = {ui_e, ue1 + Eu, ue2 + Eu, ie1 + Ei, ie2 + Ei,
                         ue1, ue2, ie1, ie2};
    const int  ce[9]  = {Eui, Eu, Eu, Ei, Ei, Eu, Eu, Ei, Ei};
    const int  cd[9]  = {OFF_DEG + RB_GCN, OFF_DEG + RB_U1, OFF_DEG + RB_U2,
                         OFF_DEG + RB_I1, OFF_DEG + RB_I2,
                         OFF_DOUT + 0, OFF_DOUT + U_N,
                         OFF_DOUT + 2 * U_N, OFF_DOUT + 2 * U_N + I_N};
    {
        int acc = 0;
        for (int k = 0; k < 9; k++) {
            cj.ptr[k] = cp[k]; cj.dego[k] = cd[k]; cj.E[k] = ce[k];
            cj.qcum[k] = acc; acc += (ce[k] + 3) / 4;
        }
        cj.qcum[9] = acc;
        initcnt_k<<<GRID_INIT + nblk(acc), T>>>((const float4*)user_feat,
                                                (const float4*)item_feat, cj);
    }

    // ---- scan -> CSR row offsets; fused cursor init + weights ----
    const int nchunks = (NSCAN + 2047) / 2048;  // 220
    scan1_k<<<nchunks, T>>>(ibuf + OFF_DEG, NSCAN, S, ibuf + OFF_PART);
    scan23w_k<<<nchunks, 256>>>(nchunks);

    // ---- fused CSR fill (4 edges/thread) ----
    FillJobs fj;
    const int* fs[5] = {ui_e + Eui, ue1, ue2, ie1, ie2};
    const int* fd[5] = {ui_e, ue1 + Eu, ue2 + Eu, ie1 + Ei, ie2 + Ei};
    const int  fe[5] = {Eui, Eu, Eu, Ei, Ei};
    const int  fb[5] = {RB_GCN, RB_U1, RB_U2, RB_I1, RB_I2};
    {
        int acc = 0;
        for (int k = 0; k < 5; k++) {
            fj.src[k] = fs[k]; fj.dst[k] = fd[k]; fj.rb[k] = fb[k]; fj.E[k] = fe[k];
            fj.qcum[k] = acc; acc += (fe[k] + 3) / 4;
        }
        fj.qcum[5] = acc;
        fill_all_k<<<nblk(acc), T>>>(fj);
    }

    // ---- 2 propagation iterations ----
    // iter 0: gcn gathers ui16_a -> ui16_b (fp16); combine writes fp16 h
    hanpull_k<<<nblk((long long)(2 * U_N + 2 * I_N) * 8), T>>>();
    gcn_attn_k<<<GRID_FUSE, 256>>>((const uint4*)ui16_a, (uint4*)ui16_b,
                                   nullptr, 0,
                                   sa_u_W1, sa_u_b1, sa_u_w2,
                                   sa_i_W1, sa_i_b1, sa_i_w2);
    combine_all_k<<<nblk((long long)(U_N + I_N) * 16), T>>>();

    // iter 1: gcn gathers ui16_b -> ui32 (fp32 epilogue source)
    hanpull_k<<<nblk((long long)(2 * U_N + 2 * I_N) * 8), T>>>();
    gcn_attn_k<<<GRID_FUSE, 256>>>((const uint4*)ui16_b, nullptr,
                                   ui32, 1,
                                   sa_u_W1, sa_u_b1, sa_u_w2,
                                   sa_i_W1, sa_i_b1, sa_i_w2);

    // ---- epilogue ----
    out_k<<<nblk((long long)B_N * 16), T>>>(uidx, iidx, nidx, (float*)d_out);
}

// round 17
// speedup vs baseline: 1.0928x; 1.0928x over previous
#include <cuda_runtime.h>
#include <cuda_bf16.h>
#include <cuda_fp16.h>
#include <cstdint>

// Problem constants (fixed by the dataset)
constexpr int U_N  = 50000;
constexpr int I_N  = 100000;
constexpr int N_N  = 150000;   // U + I
constexpr int D    = 64;
constexpr int B_N  = 8192;
constexpr int HID  = 128;

constexpr int NTOT  = N_N + 2 * U_N + 2 * I_N;   // 450000 CSR rows (5 graphs)
constexpr int NSCAN = NTOT + 1;
constexpr int E_TOT = 5000000;

// int scratch layout
constexpr int OFF_DEG  = 0;
constexpr int DEG_PAD  = 450008;
constexpr int OFF_CNT  = DEG_PAD;                // cursor array (init = S by scan23w)
constexpr int CNT_PAD  = 450008;
constexpr int OFF_DOUT = OFF_CNT + CNT_PAD;
constexpr int DOUT_LEN = 2 * U_N + 2 * I_N;      // 300000
constexpr int OFF_PART = OFF_DOUT + DOUT_LEN;
constexpr int INT_TOT  = OFF_PART + 256;

// CSR row bases within the concatenated degree/scan vector
constexpr int RB_GCN = 0;
constexpr int RB_U1  = N_N;
constexpr int RB_U2  = N_N + U_N;
constexpr int RB_I1  = N_N + 2 * U_N;
constexpr int RB_I2  = N_N + 2 * U_N + I_N;

// attention tiling (16-row tiles, 8 warps/block, one tile per warp)
constexpr int NTU   = (2 * U_N) / 16;            // 6250
constexpr int NTI   = (2 * I_N) / 16;            // 12500
constexpr int BLK_U = (NTU + 7) / 8;             // 782
constexpr int BLK_I = (NTI + 7) / 8;             // 1563
constexpr int GRID_ATTN = BLK_U + BLK_I;         // 2345
constexpr int GRID_GCN0 = (N_N * 8 + 255) / 256;      // 4688: full iter-0 pull
constexpr int GRID_GCN1 = (2 * B_N * 8 + 255) / 256;  // 512: pruned iter-1 pull
constexpr int GRID_F0   = GRID_ATTN + GRID_GCN0;
constexpr int GRID_F1   = GRID_ATTN + GRID_GCN1;

constexpr int GRID_INIT = (N_N * 16) / 256;      // 9375 (init part of initcnt)

// ---------------------------------------------------------------------------
// Scratch (device globals: allocation-free)
// ---------------------------------------------------------------------------
__device__ __align__(256) __half g_ui16_a[N_N * D];   // fp16 gather ping
__device__ __align__(256) __half g_ui16_b[N_N * D];   // fp16 gather pong
__device__ __align__(256) float  g_ui32[N_N * D];     // fp32 final gcn output (sparse)
__device__ __align__(256) __half g_hu16[U_N * D];
__device__ __align__(256) __half g_hi16[I_N * D];
__device__ __align__(256) float  g_zu[U_N * 2 * D];
__device__ __align__(256) float  g_zi[I_N * 2 * D];
__device__ __align__(256) float  g_wdst[NTOT];
__device__ __align__(256) float  g_wsrc[DOUT_LEN];
__device__ __align__(256) float  g_wsum[4];
__device__ __align__(256) int    g_int[INT_TOT];
__device__ __align__(256) int    g_S[NSCAN + 8];
__device__ __align__(256) int    g_csr[E_TOT];

// ---------------------------------------------------------------------------
// Helpers
// ---------------------------------------------------------------------------
__device__ __forceinline__ float tanh_fast(float x) {
    float y;
    asm("tanh.approx.f32 %0, %1;" : "=f"(y) : "f"(x));
    return y;
}
__device__ __forceinline__ uint32_t pack_bf16(float lo, float hi) {
    uint32_t r;
    asm("cvt.rn.bf16x2.f32 %0, %1, %2;" : "=r"(r) : "f"(hi), "f"(lo));
    return r;
}
__device__ __forceinline__ void mma16816(float c[4], const uint32_t a[4],
                                         uint32_t b0, uint32_t b1) {
    asm volatile(
        "mma.sync.aligned.m16n8k16.row.col.f32.bf16.bf16.f32 "
        "{%0,%1,%2,%3}, {%4,%5,%6,%7}, {%8,%9}, {%0,%1,%2,%3};"
        : "+f"(c[0]), "+f"(c[1]), "+f"(c[2]), "+f"(c[3])
        : "r"(a[0]), "r"(a[1]), "r"(a[2]), "r"(a[3]), "r"(b0), "r"(b1));
}
__device__ __forceinline__ float2 beta_pair(const float* __restrict__ wsum,
                                            int off, float inv_n) {
    float a = wsum[off] * inv_n;
    float b = wsum[off + 1] * inv_n;
    float m = fmaxf(a, b);
    float e0 = expf(a - m), e1 = expf(b - m);
    float inv = 1.f / (e0 + e1);
    return make_float2(e0 * inv, e1 * inv);
}

// 8 fp32 accumulator
struct f8 { float4 a, b; };
// accumulate w * (8 halves loaded as uint4) into f8
__device__ __forceinline__ void acc_h8(f8& acc, float w, const uint4* row, int lane) {
    uint4 v = row[lane];
    float2 f0 = __half22float2(*(const __half2*)&v.x);
    float2 f1 = __half22float2(*(const __half2*)&v.y);
    float2 f2 = __half22float2(*(const __half2*)&v.z);
    float2 f3 = __half22float2(*(const __half2*)&v.w);
    acc.a.x = fmaf(w, f0.x, acc.a.x); acc.a.y = fmaf(w, f0.y, acc.a.y);
    acc.a.z = fmaf(w, f1.x, acc.a.z); acc.a.w = fmaf(w, f1.y, acc.a.w);
    acc.b.x = fmaf(w, f2.x, acc.b.x); acc.b.y = fmaf(w, f2.y, acc.b.y);
    acc.b.z = fmaf(w, f3.x, acc.b.z); acc.b.w = fmaf(w, f3.y, acc.b.w);
}

// ---------------------------------------------------------------------------
// Kernels
// ---------------------------------------------------------------------------
__global__ void zero_i4_k(int4* p, int n4) {
    int t = blockIdx.x * blockDim.x + threadIdx.x;
    if (t < n4) p[t] = make_int4(0, 0, 0, 0);
}

// ---------------------------------------------------------------------------
// FUSED init + degree counting (cnt: 4 edges/thread — saturation point)
// ---------------------------------------------------------------------------
struct CntJobs {
    const int* ptr[9];
    int        dego[9];
    int        E[9];
    int        qcum[10];
};

__global__ void initcnt_k(const float4* __restrict__ uf, const float4* __restrict__ itf,
                          CntJobs J) {
    if (blockIdx.x < GRID_INIT) {
        int t = blockIdx.x * blockDim.x + threadIdx.x;   // handles 4 floats
        float4 v;
        __half2* hdst;
        int hidx;
        if (t < U_N * 16) {
            v = uf[t];
            hdst = (__half2*)g_hu16; hidx = 2 * t;
        } else {
            v = itf[t - U_N * 16];
            hdst = (__half2*)g_hi16; hidx = 2 * (t - U_N * 16);
        }
        __half2 h0 = __floats2half2_rn(v.x, v.y);
        __half2 h1 = __floats2half2_rn(v.z, v.w);
        ((__half2*)g_ui16_a)[2 * t]     = h0;
        ((__half2*)g_ui16_a)[2 * t + 1] = h1;
        hdst[hidx]     = h0;
        hdst[hidx + 1] = h1;
        return;
    }
    int t = (blockIdx.x - GRID_INIT) * blockDim.x + threadIdx.x;
    if (t >= J.qcum[9]) return;
    int j = 0;
    #pragma unroll
    for (int k = 1; k < 9; k++) j += (t >= J.qcum[k]);
    int e0 = (t - J.qcum[j]) * 4;
    int E = J.E[j];
    const int* p = J.ptr[j];
    int* base = g_int + J.dego[j];
    #pragma unroll
    for (int i = 0; i < 4; i++) {
        int e = e0 + i;
        if (e < E) atomicAdd(&base[p[e]], 1);
    }
}

// --- scan phase 1 ---
__global__ void scan1_k(const int* __restrict__ deg, int n,
                        int* __restrict__ S, int* __restrict__ part) {
    __shared__ int warpsum[8];
    int base = blockIdx.x * 2048 + threadIdx.x * 8;
    int v[8];
    int s = 0;
    #pragma unroll
    for (int i = 0; i < 8; i++) {
        int x = (base + i < n) ? deg[base + i] : 0;
        v[i] = s; s += x;
    }
    int lane = threadIdx.x & 31, w = threadIdx.x >> 5;
    int ts = s;
    #pragma unroll
    for (int o = 1; o < 32; o <<= 1) {
        int y = __shfl_up_sync(0xffffffffu, ts, o);
        if (lane >= o) ts += y;
    }
    if (lane == 31) warpsum[w] = ts;
    __syncthreads();
    if (w == 0 && lane < 8) {
        int x = warpsum[lane];
        #pragma unroll
        for (int o = 1; o < 8; o <<= 1) {
            int y = __shfl_up_sync(0xffu, x, o);
            if (lane >= o) x += y;
        }
        warpsum[lane] = x;
    }
    __syncthreads();
    int prefix = (w > 0 ? warpsum[w - 1] : 0) + (ts - s);
    #pragma unroll
    for (int i = 0; i < 8; i++)
        if (base + i < n) S[base + i] = prefix + v[i];
    if (threadIdx.x == 0) part[blockIdx.x] = warpsum[7];
}

// --- scan phase 2+3 fused with cursor init + weights ---
__global__ void scan23w_k(int nchunks) {
    __shared__ int sh[256];
    {
        int t = threadIdx.x;
        int x = (t < nchunks) ? g_int[OFF_PART + t] : 0;
        sh[t] = x;
        __syncthreads();
        for (int o = 1; o < 256; o <<= 1) {
            int y = (t >= o) ? sh[t - o] : 0;
            __syncthreads();
            sh[t] += y;
            __syncthreads();
        }
    }
    int psum = (blockIdx.x > 0) ? sh[blockIdx.x - 1] : 0;
    int base = blockIdx.x * 2048 + threadIdx.x * 8;
    #pragma unroll
    for (int i = 0; i < 8; i++) {
        int t = base + i;
        if (t >= NSCAN) break;
        int sv = g_S[t] + psum;
        g_S[t] = sv;
        if (t < NTOT) {
            g_int[OFF_CNT + t] = sv;
            float d = (float)g_int[OFF_DEG + t];
            g_wdst[t] = (t < N_N) ? ((d > 0.f) ? rsqrtf(d) : 0.f)
                                  : rsqrtf(fmaxf(d, 1.f));
        }
        if (t < DOUT_LEN)
            g_wsrc[t] = rsqrtf(fmaxf((float)g_int[OFF_DOUT + t], 1.f));
    }
}

// ---------------------------------------------------------------------------
// Fused CSR fill (4 edges/thread, direct global cursor)
// ---------------------------------------------------------------------------
struct FillJobs {
    const int* src[5];
    const int* dst[5];
    int        rb[5];
    int        E[5];
    int        qcum[6];
};

__global__ void fill_all_k(FillJobs J) {
    int t = blockIdx.x * blockDim.x + threadIdx.x;
    if (t >= J.qcum[5]) return;
    int j = 0;
    #pragma unroll
    for (int k = 1; k < 5; k++) j += (t >= J.qcum[k]);
    int e0 = (t - J.qcum[j]) * 4;
    int E = J.E[j];
    const int* src = J.src[j];
    const int* dst = J.dst[j];
    int* cur = g_int + OFF_CNT + J.rb[j];
    #pragma unroll
    for (int i = 0; i < 4; i++) {
        int e = e0 + i;
        if (e < E) {
            int p = atomicAdd(&cur[dst[e]], 1);
            g_csr[p] = src[e];
        }
    }
}

// ---------------------------------------------------------------------------
// fp16 CSR pull body: QUARTER-warp (8 lanes) per row, uint4 (16B) payload.
// 4 rows per warp -> 16 independent gathers in flight per warp. (R13 form)
// ---------------------------------------------------------------------------
__device__ __forceinline__ f8 pull_row16(const int* __restrict__ S,
                                         const int* __restrict__ csr,
                                         const float* __restrict__ wsrc,
                                         const float* __restrict__ wdst,
                                         const uint4* __restrict__ in,  // row stride 8 uint4
                                         int r, int lane) {
    int s = S[r], e = S[r + 1];
    f8 acc;
    acc.a = make_float4(0.f, 0.f, 0.f, 0.f);
    acc.b = make_float4(0.f, 0.f, 0.f, 0.f);
    int j = s;
    for (; j + 4 <= e; j += 4) {
        int c0 = csr[j], c1 = csr[j + 1], c2 = csr[j + 2], c3 = csr[j + 3];
        float w0 = wsrc[c0], w1 = wsrc[c1], w2 = wsrc[c2], w3 = wsrc[c3];
        acc_h8(acc, w0, in + (size_t)c0 * 8, lane);
        acc_h8(acc, w1, in + (size_t)c1 * 8, lane);
        acc_h8(acc, w2, in + (size_t)c2 * 8, lane);
        acc_h8(acc, w3, in + (size_t)c3 * 8, lane);
    }
    for (; j < e; j++) {
        int c = csr[j];
        acc_h8(acc, wsrc[c], in + (size_t)c * 8, lane);
    }
    float wd = wdst[r];
    acc.a.x *= wd; acc.a.y *= wd; acc.a.z *= wd; acc.a.w *= wd;
    acc.b.x *= wd; acc.b.y *= wd; acc.b.z *= wd; acc.b.w *= wd;
    return acc;
}

// ---------------------------------------------------------------------------
// Fused HAN pulls: all 4 metapath graphs (300K rows, 8 lanes/row), fp16 in,
// fp32 z out; also resets wsum for the following attention kernel.
// ---------------------------------------------------------------------------
__global__ void hanpull_k() {
    if (blockIdx.x == 0 && threadIdx.x < 4) g_wsum[threadIdx.x] = 0.f;
    int gid = blockIdx.x * blockDim.x + threadIdx.x;
    int gr = gid >> 3;   // 0 .. 300K
    if (gr >= 2 * U_N + 2 * I_N) return;
    int lane = gid & 7;
    int R = RB_U1 + gr;

    const uint4* in;
    float* out;
    const float* ws;
    int ooff, lr;
    if (gr < U_N)                { in = (const uint4*)g_hu16; out = g_zu; ws = g_wsrc;                 ooff = 0;  lr = gr; }
    else if (gr < 2 * U_N)       { in = (const uint4*)g_hu16; out = g_zu; ws = g_wsrc + U_N;           ooff = 64; lr = gr - U_N; }
    else if (gr < 2 * U_N + I_N) { in = (const uint4*)g_hi16; out = g_zi; ws = g_wsrc + 2 * U_N;       ooff = 0;  lr = gr - 2 * U_N; }
    else                         { in = (const uint4*)g_hi16; out = g_zi; ws = g_wsrc + 2 * U_N + I_N; ooff = 64; lr = gr - 2 * U_N - I_N; }

    f8 o = pull_row16(g_S, g_csr, ws, g_wdst, in, R, lane);
    float* dst = out + (size_t)lr * 128 + ooff + lane * 8;
    *(float4*)dst       = o.a;
    *(float4*)(dst + 4) = o.b;
}

// ---------------------------------------------------------------------------
// FUSED: HAN attention (user+item, tensor cores) co-resident with gcn pull.
// iter0 (last=0): full 150K-row pull, fp16 pong output.
// iter1 (last=1): PRUNED pull over only the <=16384 rows the epilogue reads
//                 ({uidx} and {U_N+iidx}); duplicates write identical bytes.
// ---------------------------------------------------------------------------
constexpr int WT_STRIDE = 72;

__global__ void gcn_attn_k(const uint4* __restrict__ ui_in16,
                           uint4* __restrict__ ui_out16,
                           float* __restrict__ ui_out32, int last,
                           const int* __restrict__ uidx, const int* __restrict__ iidx,
                           const float* __restrict__ W1u, const float* __restrict__ b1u,
                           const float* __restrict__ w2u,
                           const float* __restrict__ W1i, const float* __restrict__ b1i,
                           const float* __restrict__ w2i) {
    if (blockIdx.x >= GRID_ATTN) {
        // ---- gcn pull path ----
        int gid = (blockIdx.x - GRID_ATTN) * blockDim.x + threadIdx.x;
        int lane = gid & 7;
        if (last) {
            int t = gid >> 3;
            if (t < 2 * B_N) {
                int r = (t < B_N) ? uidx[t] : (U_N + iidx[t - B_N]);
                f8 o = pull_row16(g_S + RB_GCN, g_csr, g_wdst + RB_GCN,
                                  g_wdst + RB_GCN, ui_in16, r, lane);
                float* dst = ui_out32 + (size_t)r * D + lane * 8;
                *(float4*)dst       = o.a;
                *(float4*)(dst + 4) = o.b;
            }
        } else {
            int r = gid >> 3;
            if (r < N_N) {
                f8 o = pull_row16(g_S + RB_GCN, g_csr, g_wdst + RB_GCN,
                                  g_wdst + RB_GCN, ui_in16, r, lane);
                uint4 hv;
                *(__half2*)&hv.x = __floats2half2_rn(o.a.x, o.a.y);
                *(__half2*)&hv.y = __floats2half2_rn(o.a.z, o.a.w);
                *(__half2*)&hv.z = __floats2half2_rn(o.b.x, o.b.y);
                *(__half2*)&hv.w = __floats2half2_rn(o.b.z, o.b.w);
                ui_out16[(size_t)r * 8 + lane] = hv;
            }
        }
        return;
    }

    // ---- attention path (fp32 zu/zi, unchanged) ----
    bool isU = blockIdx.x < BLK_U;
    const float* z  = isU ? g_zu : g_zi;
    const float* W1 = isU ? W1u : W1i;
    const float* b1 = isU ? b1u : b1i;
    const float* w2 = isU ? w2u : w2i;
    int ntiles = isU ? NTU : NTI;
    int bid    = isU ? blockIdx.x : blockIdx.x - BLK_U;
    float* wsp = g_wsum + (isU ? 0 : 2);

    __shared__ __align__(16) __nv_bfloat16 Wt[HID * WT_STRIDE];
    __shared__ float b1s[HID];
    __shared__ float w2s[HID];
    __shared__ float r0s[256], r1s[256];

    for (int i = threadIdx.x; i < D * HID; i += blockDim.x) {
        int k = i >> 7, h = i & 127;
        Wt[h * WT_STRIDE + k] = __float2bfloat16(W1[i]);
    }
    if (threadIdx.x < HID) {
        b1s[threadIdx.x] = b1[threadIdx.x];
        w2s[threadIdx.x] = w2[threadIdx.x];
    }
    __syncthreads();

    int warp = threadIdx.x >> 5;
    int lane = threadIdx.x & 31;
    int g = lane >> 2;
    int tig = lane & 3;
    int tile = bid * 8 + warp;

    float acc0 = 0.f, acc1 = 0.f;

    if (tile < ntiles) {
        const float* zb = z + (size_t)tile * 16 * D;
        uint32_t A[4][4];
        #pragma unroll
        for (int kt = 0; kt < 4; kt++) {
            int k0 = kt * 16 + tig * 2;
            float2 v;
            v = *(const float2*)(zb + g * D + k0);            A[kt][0] = pack_bf16(v.x, v.y);
            v = *(const float2*)(zb + (g + 8) * D + k0);      A[kt][1] = pack_bf16(v.x, v.y);
            v = *(const float2*)(zb + g * D + k0 + 8);        A[kt][2] = pack_bf16(v.x, v.y);
            v = *(const float2*)(zb + (g + 8) * D + k0 + 8);  A[kt][3] = pack_bf16(v.x, v.y);
        }
        float s0 = 0.f, s1 = 0.f;
        #pragma unroll
        for (int nt = 0; nt < 16; nt++) {
            float c[4] = {0.f, 0.f, 0.f, 0.f};
            const __nv_bfloat16* wrow = Wt + (nt * 8 + g) * WT_STRIDE;
            #pragma unroll
            for (int kt = 0; kt < 4; kt++) {
                uint32_t b0 = *(const uint32_t*)(wrow + kt * 16 + tig * 2);
                uint32_t b1v = *(const uint32_t*)(wrow + kt * 16 + tig * 2 + 8);
                mma16816(c, A[kt], b0, b1v);
            }
            int col0 = nt * 8 + tig * 2;
            float bb0 = b1s[col0], bb1 = b1s[col0 + 1];
            float ww0 = w2s[col0], ww1 = w2s[col0 + 1];
            s0 = fmaf(tanh_fast(c[0] + bb0), ww0, s0);
            s0 = fmaf(tanh_fast(c[1] + bb1), ww1, s0);
            s1 = fmaf(tanh_fast(c[2] + bb0), ww0, s1);
            s1 = fmaf(tanh_fast(c[3] + bb1), ww1, s1);
        }
        s0 += __shfl_xor_sync(0xffffffffu, s0, 1);
        s0 += __shfl_xor_sync(0xffffffffu, s0, 2);
        s1 += __shfl_xor_sync(0xffffffffu, s1, 1);
        s1 += __shfl_xor_sync(0xffffffffu, s1, 2);
        if (tig == 0) {
            float v = s0 + s1;
            if (g & 1) acc1 += v; else acc0 += v;
        }
    }

    r0s[threadIdx.x] = acc0;
    r1s[threadIdx.x] = acc1;
    __syncthreads();
    for (int s = blockDim.x >> 1; s > 0; s >>= 1) {
        if (threadIdx.x < s) {
            r0s[threadIdx.x] += r0s[threadIdx.x + s];
            r1s[threadIdx.x] += r1s[threadIdx.x + s];
        }
        __syncthreads();
    }
    if (threadIdx.x == 0) {
        atomicAdd(&wsp[0], r0s[0]);
        atomicAdd(&wsp[1], r1s[0]);
    }
}

// ---------------------------------------------------------------------------
// Fused combine (user + item), beta inline; writes fp16 h (iteration 1 only)
// ---------------------------------------------------------------------------
__global__ void combine_all_k() {
    int t = blockIdx.x * blockDim.x + threadIdx.x;
    if (t >= (U_N + I_N) * 16) return;
    int node = t >> 4;
    int c = t & 15;
    const float4* z;
    __half2* h;
    float2 bb;
    if (node < U_N) {
        z = (const float4*)g_zu; h = (__half2*)g_hu16;
        bb = beta_pair(g_wsum, 0, 1.0f / U_N);
    } else {
        node -= U_N;
        z = (const float4*)g_zi; h = (__half2*)g_hi16;
        bb = beta_pair(g_wsum, 2, 1.0f / I_N);
    }
    float4 z0 = z[node * 32 + c];
    float4 z1 = z[node * 32 + 16 + c];
    float rx = fmaf(bb.x, z0.x, bb.y * z1.x);
    float ry = fmaf(bb.x, z0.y, bb.y * z1.y);
    float rz = fmaf(bb.x, z0.z, bb.y * z1.z);
    float rw = fmaf(bb.x, z0.w, bb.y * z1.w);
    h[node * 32 + c * 2]     = __floats2half2_rn(rx, ry);
    h[node * 32 + c * 2 + 1] = __floats2half2_rn(rz, rw);
}

// epilogue: iter-2 combine fused into the batched gathers; beta inline
__global__ void out_k(const int* __restrict__ uidx, const int* __restrict__ iidx,
                      const int* __restrict__ nidx, float* __restrict__ out) {
    int t = blockIdx.x * blockDim.x + threadIdx.x;
    if (t >= B_N * 16) return;
    int b = t >> 4;
    int c = t & 15;
    const float4* zu4 = (const float4*)g_zu;
    const float4* zi4 = (const float4*)g_zi;
    const float4* ui4 = (const float4*)g_ui32;
    float4* o4 = (float4*)out;
    float2 bU = beta_pair(g_wsum, 0, 1.0f / U_N);
    float2 bI = beta_pair(g_wsum, 2, 1.0f / I_N);

    {
        int u = uidx[b];
        float4 z0 = zu4[u * 32 + c];
        float4 z1 = zu4[u * 32 + 16 + c];
        float4 g = ui4[u * 16 + c];
        float4 r;
        r.x = 0.5f * (fmaf(bU.x, z0.x, bU.y * z1.x) + g.x);
        r.y = 0.5f * (fmaf(bU.x, z0.y, bU.y * z1.y) + g.y);
        r.z = 0.5f * (fmaf(bU.x, z0.z, bU.y * z1.z) + g.z);
        r.w = 0.5f * (fmaf(bU.x, z0.w, bU.y * z1.w) + g.w);
        o4[t] = r;
    }
    {
        int it = iidx[b];
        float4 z0 = zi4[it * 32 + c];
        float4 z1 = zi4[it * 32 + 16 + c];
        float4 g = ui4[(U_N + it) * 16 + c];
        float4 r;
        r.x = 0.5f * (fmaf(bI.x, z0.x, bI.y * z1.x) + g.x);
        r.y = 0.5f * (fmaf(bI.x, z0.y, bI.y * z1.y) + g.y);
        r.z = 0.5f * (fmaf(bI.x, z0.z, bI.y * z1.z) + g.z);
        r.w = 0.5f * (fmaf(bI.x, z0.w, bI.y * z1.w) + g.w);
        o4[B_N * 16 + t] = r;
    }
    {
        int itn = iidx[nidx[b]];
        float4 z0 = zi4[itn * 32 + c];
        float4 z1 = zi4[itn * 32 + 16 + c];
        float4 g = ui4[(U_N + itn) * 16 + c];
        float4 r;
        r.x = 0.5f * (fmaf(bI.x, z0.x, bI.y * z1.x) + g.x);
        r.y = 0.5f * (fmaf(bI.x, z0.y, bI.y * z1.y) + g.y);
        r.z = 0.5f * (fmaf(bI.x, z0.z, bI.y * z1.z) + g.z);
        r.w = 0.5f * (fmaf(bI.x, z0.w, bI.y * z1.w) + g.w);
        o4[2 * B_N * 16 + t] = r;
    }
}

// ---------------------------------------------------------------------------
// Host
// ---------------------------------------------------------------------------
static inline int nblk(long long n) { return (int)((n + 255) / 256); }

extern "C" void kernel_launch(void* const* d_in, const int* in_sizes, int n_in,
                              void* d_out, int out_size) {
    const float* user_feat = (const float*)d_in[0];
    const float* item_feat = (const float*)d_in[1];
    const float* sa_u_W1   = (const float*)d_in[2];
    const float* sa_u_b1   = (const float*)d_in[3];
    const float* sa_u_w2   = (const float*)d_in[4];
    const float* sa_i_W1   = (const float*)d_in[5];
    const float* sa_i_b1   = (const float*)d_in[6];
    const float* sa_i_w2   = (const float*)d_in[7];
    const int*   ui_e      = (const int*)d_in[8];
    const int*   ue1       = (const int*)d_in[9];
    const int*   ue2       = (const int*)d_in[10];
    const int*   ie1       = (const int*)d_in[11];
    const int*   ie2       = (const int*)d_in[12];
    const int*   uidx      = (const int*)d_in[13];
    const int*   iidx      = (const int*)d_in[14];
    const int*   nidx      = (const int*)d_in[15];

    const int Eui = in_sizes[8]  / 2;   // 2,000,000
    const int Eu  = in_sizes[9]  / 2;   //   500,000
    const int Ei  = in_sizes[11] / 2;   // 1,000,000

    __half *ui16_a, *ui16_b;
    float* ui32;
    int *ibuf, *S;
    cudaGetSymbolAddress((void**)&ui16_a, g_ui16_a);
    cudaGetSymbolAddress((void**)&ui16_b, g_ui16_b);
    cudaGetSymbolAddress((void**)&ui32,   g_ui32);
    cudaGetSymbolAddress((void**)&ibuf,   g_int);
    cudaGetSymbolAddress((void**)&S,      g_S);

    const int T = 256;

    // ---- zero int scratch ----
    zero_i4_k<<<nblk(INT_TOT / 4), T>>>((int4*)ibuf, INT_TOT / 4);

    // ---- fused init + degree counting (4 edges/thread) ----
    CntJobs cj;
    const int* cp[9]  = {ui_e, ue1 + Eu, ue2 + Eu, ie1 + Ei, ie2 + Ei,
                         ue1, ue2, ie1, ie2};
    const int  ce[9]  = {Eui, Eu, Eu, Ei, Ei, Eu, Eu, Ei, Ei};
    const int  cd[9]  = {OFF_DEG + RB_GCN, OFF_DEG + RB_U1, OFF_DEG + RB_U2,
                         OFF_DEG + RB_I1, OFF_DEG + RB_I2,
                         OFF_DOUT + 0, OFF_DOUT + U_N,
                         OFF_DOUT + 2 * U_N, OFF_DOUT + 2 * U_N + I_N};
    {
        int acc = 0;
        for (int k = 0; k < 9; k++) {
            cj.ptr[k] = cp[k]; cj.dego[k] = cd[k]; cj.E[k] = ce[k];
            cj.qcum[k] = acc; acc += (ce[k] + 3) / 4;
        }
        cj.qcum[9] = acc;
        initcnt_k<<<GRID_INIT + nblk(acc), T>>>((const float4*)user_feat,
                                                (const float4*)item_feat, cj);
    }

    // ---- scan -> CSR row offsets; fused cursor init + weights ----
    const int nchunks = (NSCAN + 2047) / 2048;  // 220
    scan1_k<<<nchunks, T>>>(ibuf + OFF_DEG, NSCAN, S, ibuf + OFF_PART);
    scan23w_k<<<nchunks, 256>>>(nchunks);

    // ---- fused CSR fill (4 edges/thread) ----
    FillJobs fj;
    const int* fs[5] = {ui_e + Eui, ue1, ue2, ie1, ie2};
    const int* fd[5] = {ui_e, ue1 + Eu, ue2 + Eu, ie1 + Ei, ie2 + Ei};
    const int  fe[5] = {Eui, Eu, Eu, Ei, Ei};
    const int  fb[5] = {RB_GCN, RB_U1, RB_U2, RB_I1, RB_I2};
    {
        int acc = 0;
        for (int k = 0; k < 5; k++) {
            fj.src[k] = fs[k]; fj.dst[k] = fd[k]; fj.rb[k] = fb[k]; fj.E[k] = fe[k];
            fj.qcum[k] = acc; acc += (fe[k] + 3) / 4;
        }
        fj.qcum[5] = acc;
        fill_all_k<<<nblk(acc), T>>>(fj);
    }

    // ---- 2 propagation iterations ----
    // iter 0: full gcn pull ui16_a -> ui16_b (fp16); combine writes fp16 h
    hanpull_k<<<nblk((long long)(2 * U_N + 2 * I_N) * 8), T>>>();
    gcn_attn_k<<<GRID_F0, 256>>>((const uint4*)ui16_a, (uint4*)ui16_b,
                                 nullptr, 0, uidx, iidx,
                                 sa_u_W1, sa_u_b1, sa_u_w2,
                                 sa_i_W1, sa_i_b1, sa_i_w2);
    combine_all_k<<<nblk((long long)(U_N + I_N) * 16), T>>>();

    // iter 1: PRUNED gcn pull (only epilogue-read rows) -> fp32 ui32
    hanpull_k<<<nblk((long long)(2 * U_N + 2 * I_N) * 8), T>>>();
    gcn_attn_k<<<GRID_F1, 256>>>((const uint4*)ui16_b, nullptr,
                                 ui32, 1, uidx, iidx,
                                 sa_u_W1, sa_u_b1, sa_u_w2,
                                 sa_i_W1, sa_i_b1, sa_i_w2);

    // ---- epilogue ----
    out_k<<<nblk((long long)B_N * 16), T>>>(uidx, iidx, nidx, (float*)d_out);
}